// round 7
// baseline (speedup 1.0000x reference)
#include <cuda_runtime.h>
#include <cstdint>
#include <math.h>

#define BATCH   16
#define NPRI    119130
#define KTOP    2000
#define KEEPK   750
#define CAP     4096
#define NBINS   16384
#define BT      (BATCH * NPRI)

// Level layout (from make_priors):
//  L0: [0,      97200)  step 8,  fw=240, 3 sizes {10,16,24}, per_row=720
//  L1: [97200, 113520)  step 16, fw=120, 2 sizes {32,48},    per_row=240
//  L2: [113520,117600)  step 32, fw=60,  2 sizes {64,96},    per_row=120
//  L3: [117600,119130)  step 64, fw=30,  3 sizes {128,192,256}, per_row=90

// ---------------- scratch (static device globals; no allocs) ----------------
__device__ uint32_t           g_bits[BT];                 // screening score bits (0 if < thr)
__device__ uint32_t           g_hist[BATCH * NBINS];      // per-batch histogram of bits>>16
__device__ int                g_boundary[BATCH];
__device__ int                g_cnt[BATCH];
__device__ unsigned long long g_cand[BATCH * CAP];
__device__ float              g_score[BATCH * KTOP];
__device__ int                g_topidx[BATCH * KTOP];
__device__ float4             g_box[BATCH * KTOP];
__device__ float              g_area[BATCH * KTOP];
__device__ unsigned long long g_mask[BATCH * KTOP * 32];  // 2000x2000 bit IoU matrix / batch
__device__ uint32_t           g_rowAny[BATCH * KTOP];

// Correctly-rounded float exp via double (CUDA double exp <1 ulp, then RN to f32).
__device__ __forceinline__ float exact_expf(float x) {
    return (float)exp((double)x);
}

// ---------------- K1: zero per-run state ----------------
__global__ void k_reset() {
    int t = blockIdx.x * blockDim.x + threadIdx.x;
    if (t < BATCH * NBINS) g_hist[t] = 0;
    if (t < BATCH)         g_cnt[t] = 0;
    if (t < BATCH * KTOP)  g_rowAny[t] = 0;
}

// ---------------- K2: screening scores (fast expf) + histogram ----------------
__global__ void k_score(const float* __restrict__ conf, const float* __restrict__ iou) {
    int t = blockIdx.x * blockDim.x + threadIdx.x;
    if (t >= BT) return;
    float2 c = ((const float2*)conf)[t];
    float m  = fmaxf(c.x, c.y);
    float e0 = expf(c.x - m);
    float e1 = expf(c.y - m);
    float cls = e1 / (e0 + e1);
    float v = iou[t];
    v = fminf(fmaxf(v, 0.0f), 1.0f);
    float s = sqrtf(cls * v);
    uint32_t bits = 0;
    if (s >= 0.3f) {
        bits = __float_as_uint(s);
        atomicAdd(&g_hist[(t / NPRI) * NBINS + (bits >> 16)], 1u);
    }
    g_bits[t] = bits;
}

// ---------------- K3: rank-2000 boundary bin per batch (with 1-bin safety margin) ----------------
__global__ void k_boundary() {
    int b = blockIdx.x;
    int tid = threadIdx.x;  // 256 threads
    __shared__ uint32_t part[256];
    const uint32_t* h = &g_hist[b * NBINS];
    uint32_t s = 0;
    int base = tid * 64;
    for (int k = 0; k < 64; k++) s += h[base + k];
    part[tid] = s;
    __syncthreads();
    if (tid == 0) {
        unsigned acc = 0;
        int boundary = 0;
        bool found = false;
        for (int c = 255; c >= 0 && !found; c--) {
            if (acc + part[c] >= (unsigned)KTOP) {
                for (int bin = c * 64 + 63; bin >= c * 64; bin--) {
                    acc += h[bin];
                    if (acc >= (unsigned)KTOP) { boundary = bin; found = true; break; }
                }
            } else {
                acc += part[c];
            }
        }
        // one-bin margin: screening exp error (~1e-7) << bin width (~2e-3)
        boundary = found ? (boundary - 1) : 0;
        g_boundary[b] = boundary > 0 ? boundary : 0;
    }
}

// ---------------- K4: compact candidates >= (boundary-1) bin ----------------
__global__ void k_compact() {
    int t = blockIdx.x * blockDim.x + threadIdx.x;
    if (t >= BT) return;
    uint32_t bits = g_bits[t];
    if (!bits) return;
    int b = t / NPRI;
    int n = t - b * NPRI;
    if ((int)(bits >> 16) < g_boundary[b]) return;
    int p = atomicAdd(&g_cnt[b], 1);
    if (p >= CAP) return;
    g_cand[b * CAP + p] = ((unsigned long long)bits << 32) | (uint32_t)(~(uint32_t)n);
}

// ---------------- K4b: exact rescore of candidates (correctly-rounded exp) ----------------
__global__ void k_rescore(const float* __restrict__ conf, const float* __restrict__ iou) {
    int b = blockIdx.x;
    int cnt = g_cnt[b];
    if (cnt > CAP) cnt = CAP;
    for (int p = threadIdx.x; p < cnt; p += blockDim.x) {
        unsigned long long key = g_cand[b * CAP + p];
        int n = (int)(~(uint32_t)key);
        size_t t = (size_t)b * NPRI + (size_t)n;
        float2 c = ((const float2*)conf)[t];
        float m  = fmaxf(c.x, c.y);
        float e0 = exact_expf(c.x - m);   // one of these is exp(0)=1 exactly
        float e1 = exact_expf(c.y - m);
        float cls = e1 / (e0 + e1);
        float v = iou[t];
        v = fminf(fmaxf(v, 0.0f), 1.0f);
        float s = sqrtf(cls * v);
        unsigned long long nk = 0ULL;
        if (s >= 0.3f)
            nk = ((unsigned long long)__float_as_uint(s) << 32) | (uint32_t)(~(uint32_t)n);
        g_cand[b * CAP + p] = nk;
    }
}

// ---------------- K5: per-batch bitonic sort of candidates, emit top 2000 ----------------
__global__ void k_sort() {
    __shared__ unsigned long long sk[CAP];
    int b = blockIdx.x, tid = threadIdx.x;  // 1024 threads
    int cnt = g_cnt[b];
    if (cnt > CAP) cnt = CAP;
    for (int i = tid; i < CAP; i += 1024)
        sk[i] = (i < cnt) ? g_cand[b * CAP + i] : 0ULL;
    __syncthreads();
    for (int k = 2; k <= CAP; k <<= 1) {
        for (int j = k >> 1; j > 0; j >>= 1) {
            for (int i = tid; i < CAP; i += 1024) {
                int ixj = i ^ j;
                if (ixj > i) {
                    bool up = ((i & k) == 0);  // descending segments
                    unsigned long long a = sk[i], c = sk[ixj];
                    if (up ? (a < c) : (a > c)) { sk[i] = c; sk[ixj] = a; }
                }
            }
            __syncthreads();
        }
    }
    for (int i = tid; i < KTOP; i += 1024) {
        unsigned long long key = sk[i];
        uint32_t bits = (uint32_t)(key >> 32);
        int n = (key == 0ULL) ? 0 : (int)(~(uint32_t)key);
        g_score[b * KTOP + i]  = __uint_as_float(bits);
        g_topidx[b * KTOP + i] = n;
    }
}

// ---------------- K6: decode only selected priors (unfused IEEE ops, exact exp) ----------------
__global__ void k_decode(const float* __restrict__ loc, float* __restrict__ out) {
    int t = blockIdx.x * blockDim.x + threadIdx.x;
    if (t >= BATCH * KTOP) return;
    int b = t / KTOP;
    int n = g_topidx[t];

    int ii, jj, step, ms;
    if (n < 97200) {
        int l = n; ii = l / 720; int r = l - ii * 720; jj = r / 3; int m = r - jj * 3;
        step = 8;  ms = (m == 0) ? 10 : ((m == 1) ? 16 : 24);
    } else if (n < 113520) {
        int l = n - 97200; ii = l / 240; int r = l - ii * 240; jj = r >> 1; int m = r & 1;
        step = 16; ms = m ? 48 : 32;
    } else if (n < 117600) {
        int l = n - 113520; ii = l / 120; int r = l - ii * 120; jj = r >> 1; int m = r & 1;
        step = 32; ms = m ? 96 : 64;
    } else {
        int l = n - 117600; ii = l / 90; int r = l - ii * 90; jj = r / 3; int m = r - jj * 3;
        step = 64; ms = (m == 0) ? 128 : ((m == 1) ? 192 : 256);
    }
    // priors built in float64 then cast to float32 (matches numpy reference)
    float px = (float)((((double)jj + 0.5) * (double)step) / 1920.0);
    float py = (float)((((double)ii + 0.5) * (double)step) / 1080.0);
    float pw = (float)((double)ms / 1920.0);
    float ph = (float)((double)ms / 1080.0);

    const float* L = loc + ((size_t)b * NPRI + (size_t)n) * 14;
    float l0 = L[0], l1 = L[1], l2 = L[2], l3 = L[3];

    float cx = __fadd_rn(px, __fmul_rn(__fmul_rn(l0, 0.1f), pw));
    float cy = __fadd_rn(py, __fmul_rn(__fmul_rn(l1, 0.1f), ph));
    float wx = __fmul_rn(pw, exact_expf(__fmul_rn(l2, 0.1f)));
    float wy = __fmul_rn(ph, exact_expf(__fmul_rn(l3, 0.2f)));
    float x1 = __fsub_rn(cx, __fmul_rn(wx, 0.5f));
    float y1 = __fsub_rn(cy, __fmul_rn(wy, 0.5f));
    float x2 = __fadd_rn(x1, wx);
    float y2 = __fadd_rn(y1, wy);

    float o0 = __fmul_rn(x1, 1920.0f), o1 = __fmul_rn(y1, 1080.0f);
    float o2 = __fmul_rn(x2, 1920.0f), o3 = __fmul_rn(y2, 1080.0f);

    float* O = out + (size_t)t * 15;
    O[0] = o0; O[1] = o1; O[2] = o2; O[3] = o3;
#pragma unroll
    for (int k = 0; k < 5; k++) {
        float lx = __fadd_rn(px, __fmul_rn(__fmul_rn(L[4 + 2 * k], 0.1f), pw));
        float ly = __fadd_rn(py, __fmul_rn(__fmul_rn(L[5 + 2 * k], 0.1f), ph));
        O[4 + 2 * k] = __fmul_rn(lx, 1920.0f);
        O[5 + 2 * k] = __fmul_rn(ly, 1080.0f);
    }

    g_box[t]  = make_float4(o0, o1, o2, o3);
    g_area[t] = __fmul_rn(fmaxf(__fsub_rn(o2, o0), 0.0f), fmaxf(__fsub_rn(o3, o1), 0.0f));
}

// ---------------- K7: upper-triangular IoU>thr bit matrix (64x64 tiles) ----------------
__global__ void k_iou() {
    int b = blockIdx.z, rt = blockIdx.y, ct = blockIdx.x;
    int tid = threadIdx.x;  // 64 threads
    int row = rt * 64 + tid;
    if (ct < rt) {  // lower triangle: just zero (serial pass ORs full rows)
        if (row < KTOP) g_mask[((size_t)b * KTOP + row) * 32 + ct] = 0ULL;
        return;
    }
    __shared__ float4 cb[64];
    __shared__ float  ca[64];
    int col0 = ct * 64;
    {
        int c = col0 + tid;
        if (c < KTOP) { cb[tid] = g_box[b * KTOP + c]; ca[tid] = g_area[b * KTOP + c]; }
        else          { cb[tid] = make_float4(0, 0, 0, 0); ca[tid] = 0.0f; }
    }
    __syncthreads();
    if (row >= KTOP) return;

    float4 mb = g_box[b * KTOP + row];
    float  ma = g_area[b * KTOP + row];
    unsigned long long bits = 0;
    int jmax = KTOP - col0; if (jmax > 64) jmax = 64;
    for (int q = 0; q < jmax; q++) {
        int j = col0 + q;
        if (j <= row) continue;
        float4 c4 = cb[q];
        float ltx = fmaxf(mb.x, c4.x), lty = fmaxf(mb.y, c4.y);
        float rbx = fminf(mb.z, c4.z), rby = fminf(mb.w, c4.w);
        float w = fmaxf(__fsub_rn(rbx, ltx), 0.0f), h = fmaxf(__fsub_rn(rby, lty), 0.0f);
        float inter = __fmul_rn(w, h);
        float den = __fadd_rn(__fsub_rn(__fadd_rn(ma, ca[q]), inter), 1e-9f);
        float iouv = __fdiv_rn(inter, den);
        if (iouv > 0.3f) bits |= (1ull << q);
    }
    g_mask[((size_t)b * KTOP + row) * 32 + ct] = bits;
    if (bits) g_rowAny[b * KTOP + row] = 1u;
}

// ---------------- K8: exact sequential greedy NMS (one warp per batch) ----------------
__global__ void k_nms(float* __restrict__ out) {
    int b = blockIdx.x;
    int lane = threadIdx.x;  // 32 threads
    __shared__ float   ssc[KTOP];
    __shared__ uint8_t sany[KTOP];
    for (int i = lane; i < KTOP; i += 32) {
        ssc[i]  = g_score[b * KTOP + i];
        sany[i] = (uint8_t)g_rowAny[b * KTOP + i];
    }
    __syncwarp();
    unsigned long long rem = 0;  // lane L owns suppression word L (64 cols each)
    int cnt = 0;
    for (int i = 0; i < KTOP; i++) {
        int w = i >> 6;
        unsigned long long word = __shfl_sync(0xffffffffu, rem, w);
        bool sup = (word >> (i & 63)) & 1ull;
        float sc = ssc[i];
        bool keep = (!sup) && (sc > 0.0f);
        if (keep) {
            cnt++;
            if (sany[i]) rem |= g_mask[((size_t)b * KTOP + i) * 32 + lane];
        }
        if (lane == 0) out[((size_t)b * KTOP + i) * 15 + 14] = (keep && cnt <= KEEPK) ? sc : 0.0f;
    }
}

// ---------------- launch ----------------
extern "C" void kernel_launch(void* const* d_in, const int* in_sizes, int n_in,
                              void* d_out, int out_size) {
    const float* loc  = (const float*)d_in[0];
    const float* conf = (const float*)d_in[1];
    const float* iou  = (const float*)d_in[2];
    float* out = (float*)d_out;
    (void)in_sizes; (void)n_in; (void)out_size;

    k_reset<<<288, 1024>>>();
    k_score<<<(BT + 255) / 256, 256>>>(conf, iou);
    k_boundary<<<BATCH, 256>>>();
    k_compact<<<(BT + 255) / 256, 256>>>();
    k_rescore<<<BATCH, 256>>>(conf, iou);
    k_sort<<<BATCH, 1024>>>();
    k_decode<<<(BATCH * KTOP + 127) / 128, 128>>>(loc, out);
    k_iou<<<dim3(32, 32, BATCH), 64>>>();
    k_nms<<<BATCH, 32>>>(out);
}

// round 9
// speedup vs baseline: 1.1689x; 1.1689x over previous
#include <cuda_runtime.h>
#include <cstdint>
#include <math.h>

#define BATCH   16
#define NPRI    119130
#define KTOP    2000
#define KEEPK   750
#define CAP     4096
#define NBINS   16384
#define BT      (BATCH * NPRI)
#define T4      (BT / 4)            // 476520, exact
#define MAXSTAGE 800

// ---------------- scratch (static device globals; zero-init, self-cleaning) ----------------
__device__ uint32_t           g_bits[BT];
__device__ uint32_t           g_hist[BATCH * NBINS];      // zeroed by k_boundary after use
__device__ int                g_boundary[BATCH];
__device__ int                g_cnt[BATCH];               // zeroed by k_select after use
__device__ unsigned long long g_cand[BATCH * CAP];
__device__ float              g_score[BATCH * KTOP];
__device__ int                g_topidx[BATCH * KTOP];
__device__ float4             g_box[BATCH * KTOP];
__device__ float              g_area[BATCH * KTOP];
// transposed: g_mask[(b*32 + word) * KTOP + row]  (coalesced stores in k_iou)
__device__ unsigned long long g_mask[BATCH * 32 * KTOP];
__device__ uint32_t           g_rowAny[BATCH * KTOP];     // zeroed by k_nms after use

__device__ __forceinline__ float exact_expf(float x) {   // correctly-rounded f32 exp
    return (float)exp((double)x);
}

// ---------------- K1: screening scores (u = cls*iou, fast math) + histogram ----------------
__global__ void k_score(const float4* __restrict__ conf4, const float4* __restrict__ iou4) {
    int t = blockIdx.x * blockDim.x + threadIdx.x;
    if (t >= T4) return;
    float4 ca = conf4[2 * t];
    float4 cb = conf4[2 * t + 1];
    float4 vv = iou4[t];
    float c0[4] = {ca.x, ca.z, cb.x, cb.z};
    float c1[4] = {ca.y, ca.w, cb.y, cb.w};
    float v4[4] = {vv.x, vv.y, vv.z, vv.w};
    uint32_t ob[4];
#pragma unroll
    for (int j = 0; j < 4; j++) {
        float m  = fmaxf(c0[j], c1[j]);
        float e0 = __expf(c0[j] - m);
        float e1 = __expf(c1[j] - m);
        float cls = __fdividef(e1, e0 + e1);
        float v = fminf(fmaxf(v4[j], 0.0f), 1.0f);
        float u = cls * v;                 // s^2 proxy; monotone in final score
        uint32_t bits = 0;
        if (u >= 0.089f) {                 // margin below exact 0.09; rescore is exact
            bits = __float_as_uint(u);
            int idx = 4 * t + j;
            int b = idx / NPRI;
            atomicAdd(&g_hist[b * NBINS + (bits >> 16)], 1u);
        }
        ob[j] = bits;
    }
    ((uint4*)g_bits)[t] = make_uint4(ob[0], ob[1], ob[2], ob[3]);
}

// ---------------- K2: rank-2000 boundary bin (1-bin margin), then self-zero hist ----------------
__global__ void k_boundary() {
    int b = blockIdx.x;
    int tid = threadIdx.x;  // 256
    __shared__ uint32_t part[256];
    uint32_t* h = &g_hist[b * NBINS];
    uint32_t s = 0;
    int base = tid * 64;
    for (int k = 0; k < 64; k++) s += h[base + k];
    part[tid] = s;
    __syncthreads();
    if (tid == 0) {
        unsigned acc = 0;
        int boundary = 0;
        bool found = false;
        for (int c = 255; c >= 0 && !found; c--) {
            if (acc + part[c] >= (unsigned)KTOP) {
                for (int bin = c * 64 + 63; bin >= c * 64; bin--) {
                    acc += h[bin];
                    if (acc >= (unsigned)KTOP) { boundary = bin; found = true; break; }
                }
            } else acc += part[c];
        }
        boundary = found ? (boundary - 1) : 0;
        g_boundary[b] = boundary > 0 ? boundary : 0;
    }
    __syncthreads();
    for (int k = 0; k < 64; k++) h[base + k] = 0;   // self-clean for next graph replay
}

// ---------------- K3: compact candidates >= boundary bin (vectorized) ----------------
__global__ void k_compact() {
    int t = blockIdx.x * blockDim.x + threadIdx.x;
    if (t >= T4) return;
    uint4 bv = ((const uint4*)g_bits)[t];
    uint32_t bb[4] = {bv.x, bv.y, bv.z, bv.w};
#pragma unroll
    for (int j = 0; j < 4; j++) {
        uint32_t bits = bb[j];
        if (!bits) continue;
        int idx = 4 * t + j;
        int b = idx / NPRI;
        int n = idx - b * NPRI;
        if ((int)(bits >> 16) < g_boundary[b]) continue;
        int p = atomicAdd(&g_cnt[b], 1);
        if (p >= CAP) continue;
        g_cand[b * CAP + p] = ((unsigned long long)bits << 32) | (uint32_t)(~(uint32_t)n);
    }
}

// ---------------- K4: exact rescore + bitonic sort, emit top-2000; self-zero g_cnt ----------------
__global__ void k_select(const float* __restrict__ conf, const float* __restrict__ iou) {
    __shared__ unsigned long long sk[CAP];
    int b = blockIdx.x, tid = threadIdx.x;  // 1024
    int cnt = g_cnt[b];
    if (cnt > CAP) cnt = CAP;
    for (int p = tid; p < CAP; p += 1024) {
        unsigned long long key = 0ULL;
        if (p < cnt) {
            int n = (int)(~(uint32_t)g_cand[b * CAP + p]);
            size_t t = (size_t)b * NPRI + (size_t)n;
            float2 c = ((const float2*)conf)[t];
            float m  = fmaxf(c.x, c.y);
            float e0 = exact_expf(c.x - m);
            float e1 = exact_expf(c.y - m);
            float cls = e1 / (e0 + e1);
            float v = iou[t];
            v = fminf(fmaxf(v, 0.0f), 1.0f);
            float s = sqrtf(cls * v);
            if (s >= 0.3f)
                key = ((unsigned long long)__float_as_uint(s) << 32) | (uint32_t)(~(uint32_t)n);
        }
        sk[p] = key;
    }
    __syncthreads();
    for (int k = 2; k <= CAP; k <<= 1) {
        for (int j = k >> 1; j > 0; j >>= 1) {
            for (int i = tid; i < CAP; i += 1024) {
                int ixj = i ^ j;
                if (ixj > i) {
                    bool up = ((i & k) == 0);
                    unsigned long long a = sk[i], c = sk[ixj];
                    if (up ? (a < c) : (a > c)) { sk[i] = c; sk[ixj] = a; }
                }
            }
            __syncthreads();
        }
    }
    for (int i = tid; i < KTOP; i += 1024) {
        unsigned long long key = sk[i];
        g_score[b * KTOP + i]  = __uint_as_float((uint32_t)(key >> 32));
        g_topidx[b * KTOP + i] = (key == 0ULL) ? 0 : (int)(~(uint32_t)key);
    }
    if (tid == 0) g_cnt[b] = 0;   // self-clean
}

// ---------------- K5: decode only selected priors (exact, unfused) ----------------
__global__ void k_decode(const float* __restrict__ loc, float* __restrict__ out) {
    int t = blockIdx.x * blockDim.x + threadIdx.x;
    if (t >= BATCH * KTOP) return;
    int b = t / KTOP;
    int n = g_topidx[t];

    int ii, jj, step, ms;
    if (n < 97200) {
        int l = n; ii = l / 720; int r = l - ii * 720; jj = r / 3; int m = r - jj * 3;
        step = 8;  ms = (m == 0) ? 10 : ((m == 1) ? 16 : 24);
    } else if (n < 113520) {
        int l = n - 97200; ii = l / 240; int r = l - ii * 240; jj = r >> 1; int m = r & 1;
        step = 16; ms = m ? 48 : 32;
    } else if (n < 117600) {
        int l = n - 113520; ii = l / 120; int r = l - ii * 120; jj = r >> 1; int m = r & 1;
        step = 32; ms = m ? 96 : 64;
    } else {
        int l = n - 117600; ii = l / 90; int r = l - ii * 90; jj = r / 3; int m = r - jj * 3;
        step = 64; ms = (m == 0) ? 128 : ((m == 1) ? 192 : 256);
    }
    float px = (float)((((double)jj + 0.5) * (double)step) / 1920.0);
    float py = (float)((((double)ii + 0.5) * (double)step) / 1080.0);
    float pw = (float)((double)ms / 1920.0);
    float ph = (float)((double)ms / 1080.0);

    const float* L = loc + ((size_t)b * NPRI + (size_t)n) * 14;
    float cx = __fadd_rn(px, __fmul_rn(__fmul_rn(L[0], 0.1f), pw));
    float cy = __fadd_rn(py, __fmul_rn(__fmul_rn(L[1], 0.1f), ph));
    float wx = __fmul_rn(pw, exact_expf(__fmul_rn(L[2], 0.1f)));
    float wy = __fmul_rn(ph, exact_expf(__fmul_rn(L[3], 0.2f)));
    float x1 = __fsub_rn(cx, __fmul_rn(wx, 0.5f));
    float y1 = __fsub_rn(cy, __fmul_rn(wy, 0.5f));
    float x2 = __fadd_rn(x1, wx);
    float y2 = __fadd_rn(y1, wy);

    float o0 = __fmul_rn(x1, 1920.0f), o1 = __fmul_rn(y1, 1080.0f);
    float o2 = __fmul_rn(x2, 1920.0f), o3 = __fmul_rn(y2, 1080.0f);

    float* O = out + (size_t)t * 15;
    O[0] = o0; O[1] = o1; O[2] = o2; O[3] = o3;
#pragma unroll
    for (int k = 0; k < 5; k++) {
        float lx = __fadd_rn(px, __fmul_rn(__fmul_rn(L[4 + 2 * k], 0.1f), pw));
        float ly = __fadd_rn(py, __fmul_rn(__fmul_rn(L[5 + 2 * k], 0.1f), ph));
        O[4 + 2 * k] = __fmul_rn(lx, 1920.0f);
        O[5 + 2 * k] = __fmul_rn(ly, 1080.0f);
    }
    g_box[t]  = make_float4(o0, o1, o2, o3);
    g_area[t] = __fmul_rn(fmaxf(__fsub_rn(o2, o0), 0.0f), fmaxf(__fsub_rn(o3, o1), 0.0f));
}

// ---------------- K6: upper-tri IoU>thr bits, div-free with exact fallback ----------------
__global__ void k_iou() {
    int b = blockIdx.z, rt = blockIdx.y, ct = blockIdx.x;
    if (ct < rt) return;                       // lower triangle never stored nor read
    int tid = threadIdx.x;                     // 64
    int row = rt * 64 + tid;
    __shared__ float4 cb[64];
    __shared__ float  ca[64];
    int col0 = ct * 64;
    {
        int c = col0 + tid;
        if (c < KTOP) { cb[tid] = g_box[b * KTOP + c]; ca[tid] = g_area[b * KTOP + c]; }
        else          { cb[tid] = make_float4(1e30f, 1e30f, -1e30f, -1e30f); ca[tid] = 0.0f; }
    }
    __syncthreads();
    if (row >= KTOP) return;

    float4 mb = g_box[b * KTOP + row];
    float  ma = g_area[b * KTOP + row];
    unsigned long long bits = 0;
#pragma unroll 8
    for (int q = 0; q < 64; q++) {
        float4 c4 = cb[q];
        float ltx = fmaxf(mb.x, c4.x), lty = fmaxf(mb.y, c4.y);
        float rbx = fminf(mb.z, c4.z), rby = fminf(mb.w, c4.w);
        float w = fmaxf(__fsub_rn(rbx, ltx), 0.0f), h = fmaxf(__fsub_rn(rby, lty), 0.0f);
        float inter = __fmul_rn(w, h);
        float den = __fadd_rn(__fsub_rn(__fadd_rn(ma, ca[q]), inter), 1e-9f);
        float d = __fmaf_rn(-0.3f, den, inter);       // sign == (iou - 0.3) outside band
        float tb = 1e-6f * den;
        bool sup;
        if (fabsf(d) <= tb) sup = (__fdiv_rn(inter, den) > 0.3f);  // rare exact fallback
        else                sup = (d > 0.0f);
        if (sup) bits |= (1ull << q);
    }
    if (rt == ct) {   // clear cols <= row within diagonal tile
        int r = row - col0;
        unsigned long long low = (r < 63) ? ((1ull << (r + 1)) - 1ull) : ~0ull;
        bits &= ~low;
    }
    g_mask[((size_t)b * 32 + ct) * KTOP + row] = bits;  // coalesced (consecutive rows)
    if (bits) g_rowAny[b * KTOP + row] = 1u;
}

// ---------------- K7: greedy NMS, smem-staged masks, replicated chunk word ----------------
#define NMS_SMEM (MAXSTAGE * 32 * 8 + KTOP * 4 + KTOP * 2 + MAXSTAGE * 2 + 32)
__global__ void k_nms(float* __restrict__ out) {
    extern __shared__ char sm[];
    unsigned long long* sMask  = (unsigned long long*)sm;                       // [MAXSTAGE*32]
    float*              ssc    = (float*)(sm + MAXSTAGE * 32 * 8);              // [KTOP]
    uint16_t*           sIdxOf = (uint16_t*)(sm + MAXSTAGE * 32 * 8 + KTOP*4);  // [KTOP]
    uint16_t*           sRows  = (uint16_t*)((char*)sIdxOf + KTOP * 2);         // [MAXSTAGE]
    int*                sS     = (int*)((char*)sRows + MAXSTAGE * 2);

    int b = blockIdx.x;
    int tid = threadIdx.x;            // 128
    int lane = tid & 31, wid = tid >> 5;

    for (int i = tid; i < KTOP; i += 128) ssc[i] = g_score[b * KTOP + i];

    if (wid == 0) {                   // build overlap-row list (warp0)
        int S = 0;
        for (int base = 0; base < KTOP; base += 32) {
            int i = base + lane;
            uint32_t any = (i < KTOP) ? g_rowAny[b * KTOP + i] : 0u;
            if (i < KTOP) g_rowAny[b * KTOP + i] = 0u;          // self-clean
            unsigned bal = __ballot_sync(0xffffffffu, any != 0);
            int pos = S + __popc(bal & ((1u << lane) - 1u));
            if (i < KTOP) {
                uint16_t v = 0xFFFF;
                if (any) {
                    if (pos < MAXSTAGE) { v = (uint16_t)pos; sRows[pos] = (uint16_t)i; }
                    else v = 0xFFFE;                            // overlap but unstaged
                }
                sIdxOf[i] = v;
            }
            S += __popc(bal);
        }
        if (lane == 0) *sS = (S < MAXSTAGE) ? S : MAXSTAGE;
    }
    __syncthreads();
    int Sst = *sS;
    for (int k = wid; k < Sst; k += 4) {                        // stage masks (4 warps)
        int row = sRows[k];
        unsigned long long v = (lane >= (row >> 6))
            ? g_mask[((size_t)b * 32 + lane) * KTOP + row] : 0ULL;
        sMask[k * 32 + lane] = v;
    }
    __syncthreads();

    if (wid == 0) {                                             // serial greedy (warp0)
        unsigned long long rem = 0;                             // lane L owns word L
        int kcnt = 0;
        for (int c = 0; c < 32; c++) {
            unsigned long long cw = __shfl_sync(0xffffffffu, rem, c);
            int nrows = KTOP - 64 * c; if (nrows > 64) nrows = 64;
            for (int k = 0; k < nrows; k++) {
                int i = 64 * c + k;
                float sc = ssc[i];
                bool sup = (cw >> k) & 1ull;
                bool keep = (!sup) && (sc > 0.0f);
                float val = 0.0f;
                if (keep) {
                    kcnt++;
                    if (kcnt <= KEEPK) val = sc;
                    uint16_t st = sIdxOf[i];
                    if (st != 0xFFFF) {
                        if (st != 0xFFFE) {
                            cw  |= sMask[st * 32 + c];
                            rem |= sMask[st * 32 + lane];
                        } else {
                            cw  |= g_mask[((size_t)b * 32 + c)    * KTOP + i];
                            rem |= g_mask[((size_t)b * 32 + lane) * KTOP + i];
                        }
                    }
                }
                if (lane == 0) ssc[i] = val;                    // reuse buffer for output
            }
        }
    }
    __syncthreads();
    for (int i = tid; i < KTOP; i += 128)
        out[((size_t)b * KTOP + i) * 15 + 14] = ssc[i];
}

// ---------------- launch ----------------
extern "C" void kernel_launch(void* const* d_in, const int* in_sizes, int n_in,
                              void* d_out, int out_size) {
    const float* loc  = (const float*)d_in[0];
    const float* conf = (const float*)d_in[1];
    const float* iou  = (const float*)d_in[2];
    float* out = (float*)d_out;
    (void)in_sizes; (void)n_in; (void)out_size;

    cudaFuncSetAttribute(k_nms, cudaFuncAttributeMaxDynamicSharedMemorySize, NMS_SMEM);

    k_score<<<(T4 + 255) / 256, 256>>>((const float4*)conf, (const float4*)iou);
    k_boundary<<<BATCH, 256>>>();
    k_compact<<<(T4 + 255) / 256, 256>>>();
    k_select<<<BATCH, 1024>>>(conf, iou);
    k_decode<<<(BATCH * KTOP + 127) / 128, 128>>>(loc, out);
    k_iou<<<dim3(32, 32, BATCH), 64>>>();
    k_nms<<<BATCH, 128, NMS_SMEM>>>(out);
}

// round 10
// speedup vs baseline: 1.6770x; 1.4347x over previous
#include <cuda_runtime.h>
#include <cstdint>
#include <math.h>

#define BATCH   16
#define NPRI    119130
#define KTOP    2000
#define KEEPK   750
#define CAP     4096
#define NBINS   16384
#define BT      (BATCH * NPRI)
#define T4      (BT / 4)            // 476520, exact
#define MAXSTAGE 800

typedef unsigned long long u64;

// ---------------- scratch (static device globals; zero-init, self-cleaning) ----------------
__device__ uint32_t g_bits[BT];
__device__ uint32_t g_hist[BATCH * NBINS];      // zeroed by k_boundary after use
__device__ int      g_boundary[BATCH];
__device__ int      g_cnt[BATCH];               // zeroed by k_select after use
__device__ u64      g_cand[BATCH * CAP];
__device__ float    g_score[BATCH * KTOP];
__device__ int      g_topidx[BATCH * KTOP];
__device__ float4   g_box[BATCH * KTOP];
__device__ float    g_area[BATCH * KTOP];
// transposed: g_mask[(b*32 + word) * KTOP + row]  (coalesced stores in k_iou)
__device__ u64      g_mask[BATCH * 32 * KTOP];
__device__ uint32_t g_rowAny[BATCH * KTOP];     // zeroed by k_nms after use

__device__ __forceinline__ float exact_expf(float x) {   // correctly-rounded f32 exp
    return (float)exp((double)x);
}

// ---------------- K1: screening scores (u = cls*iou, fast math) + histogram ----------------
__global__ void k_score(const float4* __restrict__ conf4, const float4* __restrict__ iou4) {
    int t = blockIdx.x * blockDim.x + threadIdx.x;
    if (t >= T4) return;
    float4 ca = conf4[2 * t];
    float4 cb = conf4[2 * t + 1];
    float4 vv = iou4[t];
    float c0[4] = {ca.x, ca.z, cb.x, cb.z};
    float c1[4] = {ca.y, ca.w, cb.y, cb.w};
    float v4[4] = {vv.x, vv.y, vv.z, vv.w};
    uint32_t ob[4];
#pragma unroll
    for (int j = 0; j < 4; j++) {
        float m  = fmaxf(c0[j], c1[j]);
        float e0 = __expf(c0[j] - m);
        float e1 = __expf(c1[j] - m);
        float cls = __fdividef(e1, e0 + e1);
        float v = fminf(fmaxf(v4[j], 0.0f), 1.0f);
        float u = cls * v;                 // s^2 proxy; monotone in final score
        uint32_t bits = 0;
        if (u >= 0.089f) {                 // margin below exact 0.09; rescore is exact
            bits = __float_as_uint(u);
            int idx = 4 * t + j;
            int b = idx / NPRI;
            atomicAdd(&g_hist[b * NBINS + (bits >> 16)], 1u);
        }
        ob[j] = bits;
    }
    ((uint4*)g_bits)[t] = make_uint4(ob[0], ob[1], ob[2], ob[3]);
}

// ---------------- K2: rank-2000 boundary bin (1-bin margin), then self-zero hist ----------------
__global__ void k_boundary() {
    int b = blockIdx.x;
    int tid = threadIdx.x;  // 256
    __shared__ uint32_t part[256];
    uint32_t* h = &g_hist[b * NBINS];
    uint32_t s = 0;
    int base = tid * 64;
    for (int k = 0; k < 64; k++) s += h[base + k];
    part[tid] = s;
    __syncthreads();
    if (tid == 0) {
        unsigned acc = 0;
        int boundary = 0;
        bool found = false;
        for (int c = 255; c >= 0 && !found; c--) {
            if (acc + part[c] >= (unsigned)KTOP) {
                for (int bin = c * 64 + 63; bin >= c * 64; bin--) {
                    acc += h[bin];
                    if (acc >= (unsigned)KTOP) { boundary = bin; found = true; break; }
                }
            } else acc += part[c];
        }
        boundary = found ? (boundary - 1) : 0;
        g_boundary[b] = boundary > 0 ? boundary : 0;
    }
    __syncthreads();
    for (int k = 0; k < 64; k++) h[base + k] = 0;   // self-clean for next graph replay
}

// ---------------- K3: compact candidates >= boundary bin (vectorized) ----------------
__global__ void k_compact() {
    int t = blockIdx.x * blockDim.x + threadIdx.x;
    if (t >= T4) return;
    uint4 bv = ((const uint4*)g_bits)[t];
    uint32_t bb[4] = {bv.x, bv.y, bv.z, bv.w};
#pragma unroll
    for (int j = 0; j < 4; j++) {
        uint32_t bits = bb[j];
        if (!bits) continue;
        int idx = 4 * t + j;
        int b = idx / NPRI;
        int n = idx - b * NPRI;
        if ((int)(bits >> 16) < g_boundary[b]) continue;
        int p = atomicAdd(&g_cnt[b], 1);
        if (p >= CAP) continue;
        g_cand[b * CAP + p] = ((u64)bits << 32) | (uint32_t)(~(uint32_t)n);
    }
}

// ---------------- K3b: exact rescore, wide grid (spreads FP64 exp over all SMs) ----------------
__global__ void k_rescore(const float* __restrict__ conf, const float* __restrict__ iou) {
    int t = blockIdx.x * blockDim.x + threadIdx.x;
    if (t >= BATCH * CAP) return;
    int b = t / CAP, p = t - b * CAP;
    int cnt = g_cnt[b]; if (cnt > CAP) cnt = CAP;
    if (p >= cnt) return;
    int n = (int)(~(uint32_t)g_cand[t]);
    size_t q = (size_t)b * NPRI + (size_t)n;
    float2 c = ((const float2*)conf)[q];
    float m  = fmaxf(c.x, c.y);
    float e0 = exact_expf(c.x - m);
    float e1 = exact_expf(c.y - m);
    float cls = e1 / (e0 + e1);
    float v = iou[q];
    v = fminf(fmaxf(v, 0.0f), 1.0f);
    float s = sqrtf(cls * v);
    u64 key = 0ULL;
    if (s >= 0.3f)
        key = ((u64)__float_as_uint(s) << 32) | (uint32_t)(~(uint32_t)n);
    g_cand[t] = key;
}

// ---------------- K4: bitonic sort only, emit top-2000; self-zero g_cnt ----------------
__global__ void k_select() {
    __shared__ u64 sk[CAP];
    int b = blockIdx.x, tid = threadIdx.x;  // 1024
    int cnt = g_cnt[b];
    if (cnt > CAP) cnt = CAP;
    for (int p = tid; p < CAP; p += 1024)
        sk[p] = (p < cnt) ? g_cand[b * CAP + p] : 0ULL;
    __syncthreads();
    for (int k = 2; k <= CAP; k <<= 1) {
        for (int j = k >> 1; j > 0; j >>= 1) {
            for (int i = tid; i < CAP; i += 1024) {
                int ixj = i ^ j;
                if (ixj > i) {
                    bool up = ((i & k) == 0);
                    u64 a = sk[i], c = sk[ixj];
                    if (up ? (a < c) : (a > c)) { sk[i] = c; sk[ixj] = a; }
                }
            }
            __syncthreads();
        }
    }
    for (int i = tid; i < KTOP; i += 1024) {
        u64 key = sk[i];
        g_score[b * KTOP + i]  = __uint_as_float((uint32_t)(key >> 32));
        g_topidx[b * KTOP + i] = (key == 0ULL) ? 0 : (int)(~(uint32_t)key);
    }
    if (tid == 0) g_cnt[b] = 0;   // self-clean
}

// ---------------- K5: decode only selected priors (exact, unfused) ----------------
__global__ void k_decode(const float* __restrict__ loc, float* __restrict__ out) {
    int t = blockIdx.x * blockDim.x + threadIdx.x;
    if (t >= BATCH * KTOP) return;
    int b = t / KTOP;
    int n = g_topidx[t];

    int ii, jj, step, ms;
    if (n < 97200) {
        int l = n; ii = l / 720; int r = l - ii * 720; jj = r / 3; int m = r - jj * 3;
        step = 8;  ms = (m == 0) ? 10 : ((m == 1) ? 16 : 24);
    } else if (n < 113520) {
        int l = n - 97200; ii = l / 240; int r = l - ii * 240; jj = r >> 1; int m = r & 1;
        step = 16; ms = m ? 48 : 32;
    } else if (n < 117600) {
        int l = n - 113520; ii = l / 120; int r = l - ii * 120; jj = r >> 1; int m = r & 1;
        step = 32; ms = m ? 96 : 64;
    } else {
        int l = n - 117600; ii = l / 90; int r = l - ii * 90; jj = r / 3; int m = r - jj * 3;
        step = 64; ms = (m == 0) ? 128 : ((m == 1) ? 192 : 256);
    }
    float px = (float)((((double)jj + 0.5) * (double)step) / 1920.0);
    float py = (float)((((double)ii + 0.5) * (double)step) / 1080.0);
    float pw = (float)((double)ms / 1920.0);
    float ph = (float)((double)ms / 1080.0);

    const float* L = loc + ((size_t)b * NPRI + (size_t)n) * 14;
    float cx = __fadd_rn(px, __fmul_rn(__fmul_rn(L[0], 0.1f), pw));
    float cy = __fadd_rn(py, __fmul_rn(__fmul_rn(L[1], 0.1f), ph));
    float wx = __fmul_rn(pw, exact_expf(__fmul_rn(L[2], 0.1f)));
    float wy = __fmul_rn(ph, exact_expf(__fmul_rn(L[3], 0.2f)));
    float x1 = __fsub_rn(cx, __fmul_rn(wx, 0.5f));
    float y1 = __fsub_rn(cy, __fmul_rn(wy, 0.5f));
    float x2 = __fadd_rn(x1, wx);
    float y2 = __fadd_rn(y1, wy);

    float o0 = __fmul_rn(x1, 1920.0f), o1 = __fmul_rn(y1, 1080.0f);
    float o2 = __fmul_rn(x2, 1920.0f), o3 = __fmul_rn(y2, 1080.0f);

    float* O = out + (size_t)t * 15;
    O[0] = o0; O[1] = o1; O[2] = o2; O[3] = o3;
#pragma unroll
    for (int k = 0; k < 5; k++) {
        float lx = __fadd_rn(px, __fmul_rn(__fmul_rn(L[4 + 2 * k], 0.1f), pw));
        float ly = __fadd_rn(py, __fmul_rn(__fmul_rn(L[5 + 2 * k], 0.1f), ph));
        O[4 + 2 * k] = __fmul_rn(lx, 1920.0f);
        O[5 + 2 * k] = __fmul_rn(ly, 1080.0f);
    }
    g_box[t]  = make_float4(o0, o1, o2, o3);
    g_area[t] = __fmul_rn(fmaxf(__fsub_rn(o2, o0), 0.0f), fmaxf(__fsub_rn(o3, o1), 0.0f));
}

// ---------------- K6: upper-tri IoU>thr bits, div-free with exact fallback ----------------
__global__ void k_iou() {
    int b = blockIdx.z, rt = blockIdx.y, ct = blockIdx.x;
    if (ct < rt) return;                       // lower triangle never stored nor read
    int tid = threadIdx.x;                     // 64
    int row = rt * 64 + tid;
    __shared__ float4 cb[64];
    __shared__ float  ca[64];
    int col0 = ct * 64;
    {
        int c = col0 + tid;
        if (c < KTOP) { cb[tid] = g_box[b * KTOP + c]; ca[tid] = g_area[b * KTOP + c]; }
        else          { cb[tid] = make_float4(1e30f, 1e30f, -1e30f, -1e30f); ca[tid] = 0.0f; }
    }
    __syncthreads();
    if (row >= KTOP) return;

    float4 mb = g_box[b * KTOP + row];
    float  ma = g_area[b * KTOP + row];
    u64 bits = 0;
#pragma unroll 8
    for (int q = 0; q < 64; q++) {
        float4 c4 = cb[q];
        float ltx = fmaxf(mb.x, c4.x), lty = fmaxf(mb.y, c4.y);
        float rbx = fminf(mb.z, c4.z), rby = fminf(mb.w, c4.w);
        float w = fmaxf(__fsub_rn(rbx, ltx), 0.0f), h = fmaxf(__fsub_rn(rby, lty), 0.0f);
        float inter = __fmul_rn(w, h);
        float den = __fadd_rn(__fsub_rn(__fadd_rn(ma, ca[q]), inter), 1e-9f);
        float d = __fmaf_rn(-0.3f, den, inter);       // sign == (iou - 0.3) outside band
        float tb = 1e-6f * den;
        bool sup;
        if (fabsf(d) <= tb) sup = (__fdiv_rn(inter, den) > 0.3f);  // rare exact fallback
        else                sup = (d > 0.0f);
        if (sup) bits |= (1ull << q);
    }
    if (rt == ct) {
        int r = row - col0;
        u64 low = (r < 63) ? ((1ull << (r + 1)) - 1ull) : ~0ull;
        bits &= ~low;
    }
    g_mask[((size_t)b * 32 + ct) * KTOP + row] = bits;
    if (bits) g_rowAny[b * KTOP + row] = 1u;
}

// ---------------- K7: greedy NMS — serial only over masked rows, bulk bit decisions ----------------
#define NMS_SMEM (MAXSTAGE * 32 * 8 + 3 * 32 * 8 + KTOP * 4 + KTOP * 2 + MAXSTAGE * 2 + 32 * 4 + 64)
__global__ void k_nms(float* __restrict__ out) {
    extern __shared__ char sm[];
    u64*      sMask  = (u64*)sm;                                // [MAXSTAGE*32]
    u64*      sMB    = sMask + MAXSTAGE * 32;                   // [32] masked-row bits/chunk
    u64*      sSCP   = sMB + 32;                                // [32] score>0 bits/chunk
    u64*      sKept  = sSCP + 32;                               // [32] kept bits/chunk
    float*    ssc    = (float*)(sKept + 32);                    // [KTOP]
    uint16_t* sIdxOf = (uint16_t*)(ssc + KTOP);                 // [KTOP]
    uint16_t* sRows  = sIdxOf + KTOP;                           // [MAXSTAGE]
    int*      sPref  = (int*)(sRows + MAXSTAGE);                // [32]
    int*      sS     = sPref + 32;

    int b = blockIdx.x;
    int tid = threadIdx.x;            // 128
    int lane = tid & 31, wid = tid >> 5;

    for (int i = tid; i < KTOP; i += 128) ssc[i] = g_score[b * KTOP + i];
    __syncthreads();

    if (wid == 0) {                   // build overlap-row list + per-chunk bit words
        int S = 0;
        for (int base = 0; base < KTOP; base += 32) {
            int i = base + lane;
            bool inb = (i < KTOP);
            uint32_t any = inb ? g_rowAny[b * KTOP + i] : 0u;
            if (inb) g_rowAny[b * KTOP + i] = 0u;               // self-clean
            unsigned balAny = __ballot_sync(0xffffffffu, any != 0);
            unsigned balSc  = __ballot_sync(0xffffffffu, inb && ssc[i] > 0.0f);
            if (lane == 0) {
                int c = base >> 6, half = (base >> 5) & 1;
                u64 a = ((u64)balAny) << (half * 32);
                u64 s2 = ((u64)balSc) << (half * 32);
                if (half == 0) { sMB[c] = a;  sSCP[c] = s2; }
                else           { sMB[c] |= a; sSCP[c] |= s2; }
            }
            int pos = S + __popc(balAny & ((1u << lane) - 1u));
            if (inb) {
                uint16_t v = 0xFFFF;
                if (any) {
                    if (pos < MAXSTAGE) { v = (uint16_t)pos; sRows[pos] = (uint16_t)i; }
                    else v = 0xFFFE;
                }
                sIdxOf[i] = v;
            }
            S += __popc(balAny);
        }
        if (lane == 0) *sS = (S < MAXSTAGE) ? S : MAXSTAGE;
    }
    __syncthreads();
    int Sst = *sS;
    for (int k = wid; k < Sst; k += 4) {                        // stage masks (4 warps)
        int row = sRows[k];
        sMask[k * 32 + lane] = (lane >= (row >> 6))
            ? g_mask[((size_t)b * 32 + lane) * KTOP + row] : 0ULL;
    }
    __syncthreads();

    if (wid == 0) {                   // serial greedy: touch only masked rows
        u64 rem = 0;                  // lane L owns suppression word L
        for (int c = 0; c < 32; c++) {
            u64 cw = __shfl_sync(0xffffffffu, rem, c);
            u64 mb = sMB[c];
            u64 live = sSCP[c] & ~cw;  // would-be-kept rows under current state
            u64 kept = 0;
            u64 mlive = live & mb;
            while (mlive) {
                int k = __ffsll((long long)mlive) - 1;
                u64 below = k ? ((1ull << k) - 1ull) : 0ull;
                kept |= live & below;            // unmasked keeps before k (state-neutral)
                kept |= (1ull << k);             // masked row k kept: apply its mask
                int i = c * 64 + k;
                uint16_t st = sIdxOf[i];
                u64 m_lane, m_cw;
                if (st != 0xFFFE) {
                    m_lane = sMask[(int)st * 32 + lane];
                    m_cw   = sMask[(int)st * 32 + c];
                } else {
                    m_lane = (lane >= (i >> 6)) ? g_mask[((size_t)b * 32 + lane) * KTOP + i] : 0ULL;
                    m_cw   = g_mask[((size_t)b * 32 + c) * KTOP + i];
                }
                rem |= m_lane;
                cw  |= m_cw;
                u64 above = (k < 63) ? ~((2ull << k) - 1ull) : 0ull;
                live  = live & above & ~cw;
                mlive = live & mb;
            }
            kept |= live;                        // tail of unmasked keeps
            if (lane == (c & 31)) sKept[c] = kept;
        }
        __syncwarp();
        // exclusive prefix of kept counts over chunks
        int pc = __popcll(sKept[lane]);
        int incl = pc;
        for (int off = 1; off < 32; off <<= 1) {
            int v = __shfl_up_sync(0xffffffffu, incl, off);
            if (lane >= off) incl += v;
        }
        sPref[lane] = incl - pc;
    }
    __syncthreads();
    for (int i = tid; i < KTOP; i += 128) {      // parallel rank + output
        int c = i >> 6, k = i & 63;
        u64 w = sKept[c];
        bool keep = (w >> k) & 1ull;
        u64 below = k ? ((1ull << k) - 1ull) : 0ull;
        int rank = sPref[c] + __popcll(w & below) + 1;
        float val = (keep && rank <= KEEPK) ? ssc[i] : 0.0f;
        out[((size_t)b * KTOP + i) * 15 + 14] = val;
    }
}

// ---------------- launch ----------------
extern "C" void kernel_launch(void* const* d_in, const int* in_sizes, int n_in,
                              void* d_out, int out_size) {
    const float* loc  = (const float*)d_in[0];
    const float* conf = (const float*)d_in[1];
    const float* iou  = (const float*)d_in[2];
    float* out = (float*)d_out;
    (void)in_sizes; (void)n_in; (void)out_size;

    cudaFuncSetAttribute(k_nms, cudaFuncAttributeMaxDynamicSharedMemorySize, NMS_SMEM);

    k_score<<<(T4 + 255) / 256, 256>>>((const float4*)conf, (const float4*)iou);
    k_boundary<<<BATCH, 256>>>();
    k_compact<<<(T4 + 255) / 256, 256>>>();
    k_rescore<<<(BATCH * CAP + 255) / 256, 256>>>(conf, iou);
    k_select<<<BATCH, 1024>>>();
    k_decode<<<(BATCH * KTOP + 127) / 128, 128>>>(loc, out);
    k_iou<<<dim3(32, 32, BATCH), 64>>>();
    k_nms<<<BATCH, 128, NMS_SMEM>>>(out);
}